// round 5
// baseline (speedup 1.0000x reference)
#include <cuda_runtime.h>
#include <math.h>

// Problem constants
#define NCAM   6
#define NH     8
#define EMBD   256
#define HS     32
#define L      100
#define NKEY   600
#define TQ     12
#define NQT    9

#define GTHR   256
#define ATHR   512

// GEMM tiling: vbar(200x256) = featc(200x1536) @ Wbar(1536x256)
#define KSPLIT 16
#define KSL    96
#define TILE_N 128
#define TILE_M 64

__device__ float g_part[KSPLIT * 200 * 256];

typedef unsigned long long ull;

__device__ __forceinline__ ull pk2(float lo, float hi) {
    ull r;
    asm("mov.b64 %0, {%1, %2};" : "=l"(r) : "f"(lo), "f"(hi));
    return r;
}
__device__ __forceinline__ void upk2(float& lo, float& hi, ull v) {
    asm("mov.b64 {%0, %1}, %2;" : "=f"(lo), "=f"(hi) : "l"(v));
}
__device__ __forceinline__ void fma2(ull& d, ull a, ull b) {
    asm("fma.rn.f32x2 %0, %1, %2, %0;" : "+l"(d) : "l"(a), "l"(b));
}

// ===========================================================================
// K1: split-K GEMM with inline W_v fold. 128 blocks x 256 thr. (validated)
// ===========================================================================
__global__ void __launch_bounds__(GTHR, 1)
gemm_kernel(const float* __restrict__ sff, const float* __restrict__ Wv) {
    __shared__ float As[64 * 20];
    __shared__ float Bs[16 * 128];

    const int tid = threadIdx.x;
    const int bid = blockIdx.x;

    const int cb = bid & 1;
    const int rb = (bid >> 1) & 3;
    const int kz = bid >> 3;
    const int colBase = cb * TILE_N;
    const int rowBase = rb * TILE_M;
    const int k0 = kz * KSL;

    const int tx = tid & 15;
    const int ty = tid >> 4;

    ull acc[4][4];
    #pragma unroll
    for (int i = 0; i < 4; ++i)
        #pragma unroll
        for (int j = 0; j < 4; ++j) acc[i][j] = 0ull;

    for (int kt = 0; kt < KSL; kt += 16) {
        {
            int rr = tid >> 2, k4 = tid & 3;
            float4 v = make_float4(0.f, 0.f, 0.f, 0.f);
            int r = rowBase + rr;
            if (r < 200) {
                int b = (r >= 100) ? 1 : 0;
                int l = r - 100 * b;
                int i = k0 + kt + k4 * 4;
                int cam = i >> 8, ep = i & 255;
                v = *(const float4*)&sff[(b * NCAM + cam) * 25600 + l * 256 + ep];
            }
            *(float4*)&As[rr * 20 + k4 * 4] = v;
        }
        #pragma unroll
        for (int s = tid; s < 512; s += GTHR) {
            int kk = s >> 5, c = (s & 31) * 4;
            const float* wp = Wv + (size_t)(k0 + kt + kk) * 1024 + colBase + c;
            float4 x0 = *(const float4*)(wp);
            float4 x1 = *(const float4*)(wp + 256);
            float4 x2 = *(const float4*)(wp + 512);
            float4 x3 = *(const float4*)(wp + 768);
            float4 o;
            o.x = 0.25f * (x0.x + x1.x + x2.x + x3.x);
            o.y = 0.25f * (x0.y + x1.y + x2.y + x3.y);
            o.z = 0.25f * (x0.z + x1.z + x2.z + x3.z);
            o.w = 0.25f * (x0.w + x1.w + x2.w + x3.w);
            *(float4*)&Bs[kk * 128 + c] = o;
        }
        __syncthreads();

        #pragma unroll
        for (int kk = 0; kk < 16; ++kk) {
            ull av[4];
            #pragma unroll
            for (int i = 0; i < 4; ++i) {
                float a = As[(ty * 4 + i) * 20 + kk];
                av[i] = pk2(a, a);
            }
            const ull* bp = (const ull*)&Bs[kk * 128 + tx * 8];
            ull b0 = bp[0], b1 = bp[1], b2 = bp[2], b3 = bp[3];
            #pragma unroll
            for (int i = 0; i < 4; ++i) {
                fma2(acc[i][0], av[i], b0);
                fma2(acc[i][1], av[i], b1);
                fma2(acc[i][2], av[i], b2);
                fma2(acc[i][3], av[i], b3);
            }
        }
        __syncthreads();
    }
    #pragma unroll
    for (int i = 0; i < 4; ++i) {
        int r = rowBase + ty * 4 + i;
        if (r < 200) {
            float* dst = &g_part[kz * 51200 + r * 256 + colBase + tx * 8];
            #pragma unroll
            for (int j = 0; j < 4; ++j) {
                float2 f;
                upk2(f.x, f.y, acc[i][j]);
                *(float2*)&dst[2 * j] = f;
            }
        }
    }
}

// ===========================================================================
// K2: attention, warp-specialized, no K staging. 144 blocks x 512 thr.
//   warps 0-11 : scores (50 keys each, K direct GMEM->regs) + softmax + out
//   warps 12-15: Vs split-K reduction -> smem (overlaps scores)
// ===========================================================================
// smem floats: Qt[32][16] | Vs[100][32] | S[12][600] | Ws[12][100]
#define OFF_QT  0
#define OFF_VS  512
#define OFF_S   (OFF_VS + L * HS)
#define OFF_WS  (OFF_S + TQ * NKEY)
#define SMEM_FLOATS (OFF_WS + TQ * L)
#define SMEM_BYTES  (SMEM_FLOATS * 4)

__global__ void __launch_bounds__(ATHR, 1)
attn_kernel(const float* __restrict__ sff, const float* __restrict__ bq,
            const float* __restrict__ bv, float* __restrict__ out) {
    extern __shared__ float sm[];
    float* Qt = sm + OFF_QT;   // [d][16], 12 used, pre-scaled
    float* Vs = sm + OFF_VS;   // [lp][32]
    float* S  = sm + OFF_S;    // [q][600] = exp(scores)
    float* Ws = sm + OFF_WS;   // [q][100]

    const int tid  = threadIdx.x;
    const int w    = tid >> 5;
    const int lane = tid & 31;
    const int bid  = blockIdx.x;
    const int qb = bid % NQT;
    const int h  = (bid / NQT) % NH;
    const int b  = bid / (NQT * NH);
    const int q0 = qb * TQ;

    // ---- Qt: conflict-free (address == tid), lanes with qi>=12 idle --------
    {
        int d = tid >> 4, qi = tid & 15;
        if (qi < TQ) {
            int qg = q0 + qi; if (qg > 99) qg = 99;
            Qt[tid] = bq[(b * L + qg) * 256 + h * 32 + d] * 0.17677669529663687f;
        }
    }
    __syncthreads();

    if (w < 12) {
        // ---- scores + exp for keys [w*50, w*50+50) -------------------------
        const int base = w * 50;
        #pragma unroll
        for (int rep = 0; rep < 2; ++rep) {
            int k = base + lane + rep * 32;
            if (k < base + 50) {
                int cam = k / 100, lp = k - cam * 100;
                const float4* kp = (const float4*)&sff[(b * NCAM + cam) * 25600 + lp * 256 + h * 32];
                float4 k4[8];
                #pragma unroll
                for (int i = 0; i < 8; ++i) k4[i] = kp[i];

                ull acc2[6];
                #pragma unroll
                for (int p = 0; p < 6; ++p) acc2[p] = 0ull;

                #pragma unroll
                for (int dg = 0; dg < 8; ++dg) {
                    float kv[4] = {k4[dg].x, k4[dg].y, k4[dg].z, k4[dg].w};
                    #pragma unroll
                    for (int j = 0; j < 4; ++j) {
                        int d = dg * 4 + j;
                        ull kd = pk2(kv[j], kv[j]);
                        const ull* qp = (const ull*)&Qt[d * 16];
                        #pragma unroll
                        for (int p = 0; p < 6; ++p) fma2(acc2[p], qp[p], kd);
                    }
                }
                #pragma unroll
                for (int p = 0; p < 6; ++p) {
                    float lo, hi;
                    upk2(lo, hi, acc2[p]);
                    S[(2 * p) * NKEY + k]     = __expf(lo);
                    S[(2 * p + 1) * NKEY + k] = __expf(hi);
                }
            }
        }
    } else {
        // ---- Vs: split-K reduction + folded bias (overlaps scores) ---------
        int t = tid - 384;                 // 0..127
        for (int g = t; g < L * 8; g += 128) {
            int lp = g >> 3, dg = g & 7;
            int e = h * 32 + dg * 4;
            int r = b * 100 + lp;
            float4 b0 = *(const float4*)&bv[e];
            float4 b1 = *(const float4*)&bv[e + 256];
            float4 b2 = *(const float4*)&bv[e + 512];
            float4 b3 = *(const float4*)&bv[e + 768];
            float4 a;
            a.x = 0.25f * (b0.x + b1.x + b2.x + b3.x);
            a.y = 0.25f * (b0.y + b1.y + b2.y + b3.y);
            a.z = 0.25f * (b0.z + b1.z + b2.z + b3.z);
            a.w = 0.25f * (b0.w + b1.w + b2.w + b3.w);
            #pragma unroll
            for (int kz = 0; kz < KSPLIT; ++kz) {
                float4 p = *(const float4*)&g_part[kz * 51200 + r * 256 + e];
                a.x += p.x; a.y += p.y; a.z += p.z; a.w += p.w;
            }
            *(float4*)&Vs[lp * 32 + dg * 4] = a;
        }
    }
    __syncthreads();

    // ---- softmax: warp w handles query q=w ---------------------------------
    if (w < 12) {
        const int q = w;
        float z = 0.f;
        #pragma unroll
        for (int i = lane; i < 150; i += 32) {
            float4 v = ((const float4*)&S[q * NKEY])[i];
            z += (v.x + v.y) + (v.z + v.w);
        }
        #pragma unroll
        for (int off = 16; off; off >>= 1)
            z += __shfl_xor_sync(0xffffffffu, z, off);
        float invZ = __frcp_rn(z);
        #pragma unroll
        for (int i = lane; i < L; i += 32) {
            float s6 = S[q * NKEY + i]       + S[q * NKEY + 100 + i]
                     + S[q * NKEY + 200 + i] + S[q * NKEY + 300 + i]
                     + S[q * NKEY + 400 + i] + S[q * NKEY + 500 + i];
            Ws[q * L + i] = s6 * invZ;
        }
    }
    __syncthreads();

    // ---- output: out[q,d] = sum_lp Ws[q,lp] * Vs[lp,d] ---------------------
    if (w < 12) {
        const int q = w, d = lane;
        int qg = q0 + q;
        float acc = 0.f;
        #pragma unroll 4
        for (int lp = 0; lp < L; ++lp)
            acc = fmaf(Ws[q * L + lp], Vs[lp * 32 + d], acc);
        if (qg < 100)
            out[(b * L + qg) * 256 + h * 32 + d] = acc;
    }
}

// ---------------------------------------------------------------------------
extern "C" void kernel_launch(void* const* d_in, const int* in_sizes, int n_in,
                              void* d_out, int out_size) {
    const float* sff = (const float*)d_in[0];
    const float* bq  = (const float*)d_in[1];
    const float* Wv  = (const float*)d_in[2];
    const float* bv  = (const float*)d_in[3];
    float* out = (float*)d_out;

    cudaFuncSetAttribute(attn_kernel, cudaFuncAttributeMaxDynamicSharedMemorySize,
                         SMEM_BYTES);
    gemm_kernel<<<128, GTHR>>>(sff, Wv);
    attn_kernel<<<NQT * NH * 2, ATHR, SMEM_BYTES>>>(sff, bq, bv, out);
}

// round 6
// speedup vs baseline: 1.4924x; 1.4924x over previous
#include <cuda_runtime.h>
#include <math.h>

// Problem constants
#define NCAM   6
#define NH     8
#define EMBD   256
#define HS     32
#define L      100
#define NKEY   600
#define TQ     12
#define NQT    9

#define GTHR   256
#define ATHR   512

// GEMM tiling: vbar(200x256) = featc(200x1536) @ Wbar(1536x256)
#define KSPLIT 16
#define KSL    96
#define TILE_N 128
#define TILE_M 64

__device__ float g_part[KSPLIT * 200 * 256];

typedef unsigned long long ull;

__device__ __forceinline__ ull pk2(float lo, float hi) {
    ull r;
    asm("mov.b64 %0, {%1, %2};" : "=l"(r) : "f"(lo), "f"(hi));
    return r;
}
__device__ __forceinline__ void upk2(float& lo, float& hi, ull v) {
    asm("mov.b64 {%0, %1}, %2;" : "=f"(lo), "=f"(hi) : "l"(v));
}
__device__ __forceinline__ void fma2(ull& d, ull a, ull b) {
    asm("fma.rn.f32x2 %0, %1, %2, %0;" : "+l"(d) : "l"(a), "l"(b));
}

// ===========================================================================
// K1: split-K GEMM with inline W_v fold. 128 blocks x 256 thr. (validated)
// ===========================================================================
__global__ void __launch_bounds__(GTHR, 1)
gemm_kernel(const float* __restrict__ sff, const float* __restrict__ Wv) {
    __shared__ float As[64 * 20];
    __shared__ float Bs[16 * 128];

    const int tid = threadIdx.x;
    const int bid = blockIdx.x;

    const int cb = bid & 1;
    const int rb = (bid >> 1) & 3;
    const int kz = bid >> 3;
    const int colBase = cb * TILE_N;
    const int rowBase = rb * TILE_M;
    const int k0 = kz * KSL;

    const int tx = tid & 15;
    const int ty = tid >> 4;

    ull acc[4][4];
    #pragma unroll
    for (int i = 0; i < 4; ++i)
        #pragma unroll
        for (int j = 0; j < 4; ++j) acc[i][j] = 0ull;

    for (int kt = 0; kt < KSL; kt += 16) {
        {
            int rr = tid >> 2, k4 = tid & 3;
            float4 v = make_float4(0.f, 0.f, 0.f, 0.f);
            int r = rowBase + rr;
            if (r < 200) {
                int b = (r >= 100) ? 1 : 0;
                int l = r - 100 * b;
                int i = k0 + kt + k4 * 4;
                int cam = i >> 8, ep = i & 255;
                v = *(const float4*)&sff[(b * NCAM + cam) * 25600 + l * 256 + ep];
            }
            *(float4*)&As[rr * 20 + k4 * 4] = v;
        }
        #pragma unroll
        for (int s = tid; s < 512; s += GTHR) {
            int kk = s >> 5, c = (s & 31) * 4;
            const float* wp = Wv + (size_t)(k0 + kt + kk) * 1024 + colBase + c;
            float4 x0 = *(const float4*)(wp);
            float4 x1 = *(const float4*)(wp + 256);
            float4 x2 = *(const float4*)(wp + 512);
            float4 x3 = *(const float4*)(wp + 768);
            float4 o;
            o.x = 0.25f * (x0.x + x1.x + x2.x + x3.x);
            o.y = 0.25f * (x0.y + x1.y + x2.y + x3.y);
            o.z = 0.25f * (x0.z + x1.z + x2.z + x3.z);
            o.w = 0.25f * (x0.w + x1.w + x2.w + x3.w);
            *(float4*)&Bs[kk * 128 + c] = o;
        }
        __syncthreads();

        #pragma unroll
        for (int kk = 0; kk < 16; ++kk) {
            ull av[4];
            #pragma unroll
            for (int i = 0; i < 4; ++i) {
                float a = As[(ty * 4 + i) * 20 + kk];
                av[i] = pk2(a, a);
            }
            const ull* bp = (const ull*)&Bs[kk * 128 + tx * 8];
            ull b0 = bp[0], b1 = bp[1], b2 = bp[2], b3 = bp[3];
            #pragma unroll
            for (int i = 0; i < 4; ++i) {
                fma2(acc[i][0], av[i], b0);
                fma2(acc[i][1], av[i], b1);
                fma2(acc[i][2], av[i], b2);
                fma2(acc[i][3], av[i], b3);
            }
        }
        __syncthreads();
    }
    #pragma unroll
    for (int i = 0; i < 4; ++i) {
        int r = rowBase + ty * 4 + i;
        if (r < 200) {
            float* dst = &g_part[kz * 51200 + r * 256 + colBase + tx * 8];
            #pragma unroll
            for (int j = 0; j < 4; ++j) {
                float2 f;
                upk2(f.x, f.y, acc[i][j]);
                *(float2*)&dst[2 * j] = f;
            }
        }
    }
}

// ===========================================================================
// K2: attention. 144 blocks x 512 thr. K staged coalesced into swizzled
// k-major smem rows (STS.128/LDS.128); scores vectorized; no-max softmax.
// ===========================================================================
// smem floats: Qt[32][16] | Kt[600][32] swizzled | Vs[100][32] | S[12][600] | Ws[12][100]
#define OFF_QT  0
#define OFF_KT  512
#define OFF_VS  (OFF_KT + NKEY * 32)
#define OFF_S   (OFF_VS + L * HS)
#define OFF_WS  (OFF_S + TQ * NKEY)
#define SMEM_FLOATS (OFF_WS + TQ * L)
#define SMEM_BYTES  (SMEM_FLOATS * 4)

__global__ void __launch_bounds__(ATHR, 1)
attn_kernel(const float* __restrict__ sff, const float* __restrict__ bq,
            const float* __restrict__ bv, float* __restrict__ out) {
    extern __shared__ float sm[];
    float* Qt = sm + OFF_QT;   // [d][16], 12 used, pre-scaled
    float* Kt = sm + OFF_KT;   // [k][32], 16B-group swizzled: slot = g ^ (k&7)
    float* Vs = sm + OFF_VS;   // [lp][32]
    float* S  = sm + OFF_S;    // [q][600] = exp(scores)
    float* Ws = sm + OFF_WS;   // [q][100]

    const int tid  = threadIdx.x;
    const int w    = tid >> 5;
    const int lane = tid & 31;
    const int bid  = blockIdx.x;
    const int qb = bid % NQT;
    const int h  = (bid / NQT) % NH;
    const int b  = bid / (NQT * NH);
    const int q0 = qb * TQ;

    // ---- Keys: coalesced float4 loads -> swizzled STS.128 ------------------
    for (int idx = tid; idx < NKEY * 8; idx += ATHR) {
        int k = idx >> 3, g = idx & 7;
        int cam = k / 100, lp = k - cam * 100;
        float4 v = *(const float4*)&sff[(b * NCAM + cam) * 25600 + lp * 256 + h * 32 + g * 4];
        int slot = g ^ (k & 7);
        *(float4*)&Kt[k * 32 + slot * 4] = v;
    }
    // ---- Values: float4 reduction of 16 split-K partials + folded bias -----
    for (int idx = tid; idx < L * 8; idx += ATHR) {
        int lp = idx >> 3, dg = idx & 7;
        int e = h * 32 + dg * 4;
        int r = b * 100 + lp;
        float4 b0 = *(const float4*)&bv[e];
        float4 b1 = *(const float4*)&bv[e + 256];
        float4 b2 = *(const float4*)&bv[e + 512];
        float4 b3 = *(const float4*)&bv[e + 768];
        float4 a;
        a.x = 0.25f * (b0.x + b1.x + b2.x + b3.x);
        a.y = 0.25f * (b0.y + b1.y + b2.y + b3.y);
        a.z = 0.25f * (b0.z + b1.z + b2.z + b3.z);
        a.w = 0.25f * (b0.w + b1.w + b2.w + b3.w);
        #pragma unroll
        for (int kz = 0; kz < KSPLIT; ++kz) {
            float4 p = *(const float4*)&g_part[kz * 51200 + r * 256 + e];
            a.x += p.x; a.y += p.y; a.z += p.z; a.w += p.w;
        }
        *(float4*)&Vs[lp * 32 + dg * 4] = a;
    }
    // ---- Queries: Qt[d][16], pre-scaled, clamped ragged tail ---------------
    {
        int d = tid >> 4, qi = tid & 15;
        if (qi < TQ) {
            int qg = q0 + qi; if (qg > 99) qg = 99;
            Qt[tid] = bq[(b * L + qg) * 256 + h * 32 + d] * 0.17677669529663687f;
        }
    }
    __syncthreads();

    // ---- scores + exp: thread owns keys k0=tid, k1=tid+512 -----------------
    {
        const int k0i = tid;
        const int k1i = tid + 512;
        const bool has1 = (k1i < NKEY);
        const int sw0 = k0i & 7;           // (k1i & 7) == sw0 since 512 % 8 == 0
        ull acc0[6], acc1[6];
        #pragma unroll
        for (int p = 0; p < 6; ++p) { acc0[p] = 0ull; acc1[p] = 0ull; }

        #pragma unroll
        for (int g = 0; g < 8; ++g) {
            float4 kv0 = *(const float4*)&Kt[k0i * 32 + (g ^ sw0) * 4];
            float4 kv1 = has1 ? *(const float4*)&Kt[k1i * 32 + (g ^ sw0) * 4]
                              : make_float4(0.f, 0.f, 0.f, 0.f);
            const float kj0[4] = {kv0.x, kv0.y, kv0.z, kv0.w};
            const float kj1[4] = {kv1.x, kv1.y, kv1.z, kv1.w};
            #pragma unroll
            for (int j = 0; j < 4; ++j) {
                int d = g * 4 + j;
                ull kd0 = pk2(kj0[j], kj0[j]);
                ull kd1 = pk2(kj1[j], kj1[j]);
                #pragma unroll
                for (int pp = 0; pp < 3; ++pp) {
                    ulonglong2 qq = *(const ulonglong2*)&Qt[d * 16 + pp * 4];
                    fma2(acc0[2 * pp],     qq.x, kd0);
                    fma2(acc0[2 * pp + 1], qq.y, kd0);
                    fma2(acc1[2 * pp],     qq.x, kd1);
                    fma2(acc1[2 * pp + 1], qq.y, kd1);
                }
            }
        }
        #pragma unroll
        for (int p = 0; p < 6; ++p) {
            float lo, hi;
            upk2(lo, hi, acc0[p]);
            S[(2 * p) * NKEY + k0i]     = __expf(lo);
            S[(2 * p + 1) * NKEY + k0i] = __expf(hi);
            if (has1) {
                upk2(lo, hi, acc1[p]);
                S[(2 * p) * NKEY + k1i]     = __expf(lo);
                S[(2 * p + 1) * NKEY + k1i] = __expf(hi);
            }
        }
    }
    __syncthreads();

    // ---- softmax: warp w handles query q=w ---------------------------------
    if (w < 12) {
        const int q = w;
        float z = 0.f;
        #pragma unroll
        for (int i = lane; i < 150; i += 32) {
            float4 v = ((const float4*)&S[q * NKEY])[i];
            z += (v.x + v.y) + (v.z + v.w);
        }
        #pragma unroll
        for (int off = 16; off; off >>= 1)
            z += __shfl_xor_sync(0xffffffffu, z, off);
        float invZ = __frcp_rn(z);
        #pragma unroll
        for (int i = lane; i < L; i += 32) {
            float s6 = S[q * NKEY + i]       + S[q * NKEY + 100 + i]
                     + S[q * NKEY + 200 + i] + S[q * NKEY + 300 + i]
                     + S[q * NKEY + 400 + i] + S[q * NKEY + 500 + i];
            Ws[q * L + i] = s6 * invZ;
        }
    }
    __syncthreads();

    // ---- output: out[q,d] = sum_lp Ws[q,lp] * Vs[lp,d] ---------------------
    if (w < 12) {
        const int q = w, d = lane;
        int qg = q0 + q;
        float acc = 0.f;
        #pragma unroll 4
        for (int lp = 0; lp < L; ++lp)
            acc = fmaf(Ws[q * L + lp], Vs[lp * 32 + d], acc);
        if (qg < 100)
            out[(b * L + qg) * 256 + h * 32 + d] = acc;
    }
}

// ---------------------------------------------------------------------------
extern "C" void kernel_launch(void* const* d_in, const int* in_sizes, int n_in,
                              void* d_out, int out_size) {
    const float* sff = (const float*)d_in[0];
    const float* bq  = (const float*)d_in[1];
    const float* Wv  = (const float*)d_in[2];
    const float* bv  = (const float*)d_in[3];
    float* out = (float*)d_out;

    cudaFuncSetAttribute(attn_kernel, cudaFuncAttributeMaxDynamicSharedMemorySize,
                         SMEM_BYTES);
    gemm_kernel<<<128, GTHR>>>(sff, Wv);
    attn_kernel<<<NQT * NH * 2, ATHR, SMEM_BYTES>>>(sff, bq, bv, out);
}